// round 17
// baseline (speedup 1.0000x reference)
#include <cuda_runtime.h>
#include <cuda_bf16.h>
#include <cstdint>

// ---------------------------------------------------------------------------
// FeatureAlign via mma.sync bf16 (HMMA) with fp32->bf16 hi/lo splitting.
//   Y = relu( A(fp32 gathered) @ W(fp32) + b ) * mask
//   A@W ~= Ah@Wh + Ah@Wl + Al@Wh   (fp32 accum)
// GEMM: BMM=64, 4 warps/CTA, 2-stage cp.async, 4 CTAs/SM; inner loop issues
//   MMAs in 3 passes over n8 so consecutive MMAs hit different accumulators.
// deform: fused offset conv + gather + split; 8-row/128-thread blocks, 8 CTAs/SM.
// ---------------------------------------------------------------------------

#define BSZ 8
#define CCH 512
#define KT  3
#define ROWS_TOTAL 28672
#define LV0 16384
#define LV01 24576
#define KRED 1536

// GEMM tiling
#define BMM 64
#define BNN 128
#define BKK 32
#define AST 40
#define BST 136
#define A_ELE (BMM*AST)             // 2560
#define B_ELE (BKK*BST)             // 4352
#define STG_BYTES ((2*A_ELE + 2*B_ELE)*2)   // 27648 B per stage
#define NSTAGE 2
#define GEMM_SMEM (NSTAGE*STG_BYTES)        // 55296 B; 4 CTAs/SM
#define KITERS (KRED/BKK)           // 48
#define TPAD 68                     // fp32 out-tile row stride (16B aligned)

// deform kernel: 8 rows/block, 10 staged rows, 128 threads, 8 CTAs/SM
#define DROWS 8
#define DSTG  10
#define DEF_SMEM ((DSTG*CCH + DROWS*3) * 4)   // 20576 B

#define TIN_BLOCKS 14336                    // 112*16*8
#define WSPLIT_ELEMS (2*KRED*CCH)
#define OW2_ELEMS (2*KT*KT*CCH)
#define WSPLIT_TOTAL (WSPLIT_ELEMS + OW2_ELEMS + ROWS_TOTAL)

// scratch (device globals; no runtime allocation allowed)
__device__ float g_x[ROWS_TOTAL * CCH];
__device__ float g_y[ROWS_TOTAL * CCH];
__device__ float g_offa[ROWS_TOTAL * 4];
__device__ float g_mrow[ROWS_TOTAL];
__device__ float g_ow2[OW2_ELEMS];                  // transposed offset weights
__device__ __nv_bfloat16 g_Ah[(size_t)ROWS_TOTAL * KRED];
__device__ __nv_bfloat16 g_Al[(size_t)ROWS_TOTAL * KRED];
__device__ __nv_bfloat16 g_Wh[2 * KRED * CCH];
__device__ __nv_bfloat16 g_Wl[2 * KRED * CCH];

// ---------------------------------------------------------------------------
__device__ __forceinline__ uint32_t smem_u32(const void* p) {
    return (uint32_t)__cvta_generic_to_shared(p);
}
#define CP16(sa, gp) \
    asm volatile("cp.async.cg.shared.global [%0], [%1], 16;" :: "r"(sa), "l"(gp))
#define CP_COMMIT() asm volatile("cp.async.commit_group;")
#define CP_WAIT0()  asm volatile("cp.async.wait_group 0;")

__device__ __forceinline__ void ldsm_x4(uint32_t* r, uint32_t a) {
    asm volatile("ldmatrix.sync.aligned.m8n8.x4.shared.b16 {%0,%1,%2,%3}, [%4];"
                 : "=r"(r[0]), "=r"(r[1]), "=r"(r[2]), "=r"(r[3]) : "r"(a));
}
__device__ __forceinline__ void ldsm_x4_t(uint32_t* r, uint32_t a) {
    asm volatile("ldmatrix.sync.aligned.m8n8.x4.trans.shared.b16 {%0,%1,%2,%3}, [%4];"
                 : "=r"(r[0]), "=r"(r[1]), "=r"(r[2]), "=r"(r[3]) : "r"(a));
}
__device__ __forceinline__ void mma16816(float* d, const uint32_t* a,
                                         const uint32_t* b) {
    asm volatile("mma.sync.aligned.m16n8k16.row.col.f32.bf16.bf16.f32 "
                 "{%0,%1,%2,%3}, {%4,%5,%6,%7}, {%8,%9}, {%0,%1,%2,%3};"
                 : "+f"(d[0]), "+f"(d[1]), "+f"(d[2]), "+f"(d[3])
                 : "r"(a[0]), "r"(a[1]), "r"(a[2]), "r"(a[3]), "r"(b[0]), "r"(b[1]));
}

// ---------------------------------------------------------------------------
// input transposes: feats (B,C,T) per level -> concatenated rows (m, C)
__global__ void tin_kernel(const float* __restrict__ f0,
                           const float* __restrict__ f1,
                           const float* __restrict__ f2,
                           float* __restrict__ xb) {
    __shared__ float tile[32][33];
    int bid = blockIdx.x, tid = threadIdx.x;
    int xv = bid % 112;
    int y  = (bid / 112) % 16;
    int b  = bid / (112 * 16);
    int lv, xs, T, lbase;
    if (xv < 64)      { lv = 0; xs = xv;      T = 2048; lbase = 0;    }
    else if (xv < 96) { lv = 1; xs = xv - 64; T = 1024; lbase = LV0;  }
    else              { lv = 2; xs = xv - 96; T = 512;  lbase = LV01; }
    const float* f = (lv == 0) ? f0 : (lv == 1 ? f1 : f2);
    int tx = tid & 31, ty = tid >> 5;
    int s0 = xs * 32, r0 = y * 32;
    const float* inb = f + (size_t)b * CCH * T;
    float* outb = xb + (size_t)(lbase + b * T) * CCH;
    #pragma unroll
    for (int i = ty; i < 32; i += 8)
        tile[i][tx] = inb[(size_t)(r0 + i) * T + s0 + tx];
    __syncthreads();
    #pragma unroll
    for (int i = ty; i < 32; i += 8)
        outb[(size_t)(s0 + i) * CCH + r0 + tx] = tile[tx][i];
}

// weight bf16 hi/lo split + transposed offset weights + mask rows/bool out
__global__ void wsplit_kernel(const float* __restrict__ w0,
                              const float* __restrict__ w1,
                              const float* __restrict__ ow0,
                              const float* __restrict__ ow1,
                              const float* __restrict__ m0,
                              const float* __restrict__ m1,
                              const float* __restrict__ m2,
                              __nv_bfloat16* __restrict__ Wh,
                              __nv_bfloat16* __restrict__ Wl,
                              float* __restrict__ ow2,
                              float* __restrict__ mrow,
                              float* __restrict__ out) {
    int idx = blockIdx.x * blockDim.x + threadIdx.x;
    if (idx < WSPLIT_ELEMS) {
        int n = idx & 511;
        int k = (idx >> 9) % KRED;
        int l = idx / (KRED * CCH);
        int ktap = k >> 9, c = k & 511;
        const float* w = l ? w1 : w0;
        float val = w[(n * CCH + c) * KT + ktap];
        __nv_bfloat16 hi = __float2bfloat16(val);
        Wh[idx] = hi;
        Wl[idx] = __float2bfloat16(val - __bfloat162float(hi));
    } else if (idx < WSPLIT_ELEMS + OW2_ELEMS) {
        int i = idx - WSPLIT_ELEMS;
        int l = i / (KT * KT * CCH);
        int r = i % (KT * KT * CCH);     // source: (kk*512 + c)*3 + j
        int j = r % 3;
        int q = r / 3;
        int kk = q >> 9, c = q & 511;
        const float* ow = l ? ow1 : ow0;
        ow2[l * (KT * KT * CCH) + (kk * 3 + j) * CCH + c] = ow[r];
    } else if (idx < WSPLIT_TOTAL) {
        int m = idx - WSPLIT_ELEMS - OW2_ELEMS;
        float v = (m < LV0) ? m0[m] : (m < LV01 ? m1[m - LV0] : m2[m - LV01]);
        mrow[m] = v;
        out[(size_t)BSZ * CCH * 3584 + m] = (v != 0.f) ? 1.0f : 0.0f;
    }
}

// ---------------------------------------------------------------------------
// FUSED deform kernel: offset conv + im2col gather + bf16 split.
// Block = 8 rows (one level), 128 threads, 8 CTAs/SM.
template <bool EXT>
__global__ __launch_bounds__(128, 8)
void deform_kernel(const float* __restrict__ X,
                   const float* __restrict__ o0,
                   const float* __restrict__ o1,
                   const float* __restrict__ o2,
                   const float* __restrict__ ow2,
                   const float* __restrict__ ob,
                   float* __restrict__ off_out,
                   __nv_bfloat16* __restrict__ Ah,
                   __nv_bfloat16* __restrict__ Al) {
    extern __shared__ float sdyn[];
    float* xs = sdyn;                                   // 10*512
    float* off_sh = sdyn + DSTG * CCH;                  // 24
    int tid = threadIdx.x;

    int rl0g = blockIdx.x * DROWS;
    int lv = (rl0g < LV0) ? 0 : (rl0g < LV01 ? 1 : 2);
    int lbase = (lv == 0) ? 0 : (lv == 1 ? LV0 : LV01);
    int logT = 11 - lv;
    int T = 1 << logT;
    int rl0 = rl0g - lbase;
    const float* Xl = X + (size_t)lbase * CCH;

    int t0 = rl0 & (T - 1);
    for (int fi = tid; fi < DSTG * 128; fi += 128) {
        int j = fi >> 7;
        int cf = (fi & 127) * 4;
        int t = t0 + j - 1;
        float4 v = make_float4(0.f, 0.f, 0.f, 0.f);
        if (t >= 0 && t < T)
            v = *(const float4*)(Xl + (size_t)(rl0 - 1 + j) * CCH + cf);
        *(float4*)(xs + j * CCH + cf) = v;
    }
    __syncthreads();

    int warp = tid >> 5, lane = tid & 31;
    int r0l = warp * 2;

    // ---- phase 1: offset conv ----
    {
        float acc[2][3];
        #pragma unroll
        for (int i = 0; i < 2; i++)
            #pragma unroll
            for (int kk = 0; kk < 3; kk++) acc[i][kk] = 0.f;

        #pragma unroll
        for (int q = 0; q < 4; q++) {
            int c = lane * 4 + q * 128;
            float4 xv[4];
            #pragma unroll
            for (int u = 0; u < 4; u++)
                xv[u] = *(const float4*)(xs + (r0l + u) * CCH + c);
            #pragma unroll
            for (int kk = 0; kk < 3; kk++) {
                float4 wv[3];
                #pragma unroll
                for (int j = 0; j < 3; j++)
                    wv[j] = *(const float4*)(ow2 + (kk * 3 + j) * CCH + c);
                #pragma unroll
                for (int i = 0; i < 2; i++) {
                    float s = 0.f;
                    #pragma unroll
                    for (int j = 0; j < 3; j++) {
                        float4 wf = wv[j];
                        float4 xf = xv[i + j];
                        s += wf.x * xf.x + wf.y * xf.y + wf.z * xf.z + wf.w * xf.w;
                    }
                    acc[i][kk] += s;
                }
            }
        }

        #pragma unroll
        for (int i = 0; i < 2; i++)
            #pragma unroll
            for (int kk = 0; kk < 3; kk++)
                #pragma unroll
                for (int s = 16; s; s >>= 1)
                    acc[i][kk] += __shfl_down_sync(0xffffffffu, acc[i][kk], s);

        if (lane == 0) {
            #pragma unroll
            for (int i = 0; i < 2; i++) {
                int rl = rl0 + r0l + i;
                int b = rl >> logT, t = rl & (T - 1);
                int m = rl0g + r0l + i;
                float i0, i1, i2;
                if (EXT) {
                    const float* oin = (lv == 0) ? o0 : (lv == 1 ? o1 : o2);
                    i0 = oin[((size_t)b * KT + 0) * T + t];
                    i1 = oin[((size_t)b * KT + 1) * T + t];
                    i2 = oin[((size_t)b * KT + 2) * T + t];
                } else {
                    i0 = o0[(size_t)m * 4 + 0];
                    i1 = o0[(size_t)m * 4 + 1];
                    i2 = o0[(size_t)m * 4 + 2];
                }
                float v0 = acc[i][0] + ob[0] + i0;
                float v1 = acc[i][1] + ob[1] + i1;
                float v2 = acc[i][2] + ob[2] + i2;
                off_sh[(r0l + i) * 3 + 0] = v0;
                off_sh[(r0l + i) * 3 + 1] = v1;
                off_sh[(r0l + i) * 3 + 2] = v2;
                if (EXT) {
                    off_out[(size_t)m * 4 + 0] = v0;
                    off_out[(size_t)m * 4 + 1] = v1;
                    off_out[(size_t)m * 4 + 2] = v2;
                }
            }
        }
    }
    __syncthreads();

    // ---- phase 2: gather + lerp + bf16 hi/lo split; 6 (row,tap) pairs/warp
    #pragma unroll 2
    for (int pi = 0; pi < 6; pi++) {
        int pair = warp * 6 + pi;           // 0..23
        int r = pair / 3, k = pair % 3;
        int rl = rl0 + r;
        int b = rl >> logT, t = rl & (T - 1);
        int m = rl0g + r;

        float off = off_sh[r * 3 + k];
        float pos = (float)(t + k - 1) + off;
        float p0f = floorf(pos);
        float f = pos - p0f;
        int i0 = (int)p0f, i1 = i0 + 1;
        float w0 = (i0 >= 0 && i0 < T) ? (1.0f - f) : 0.0f;
        float w1 = (i1 >= 0 && i1 < T) ? f : 0.0f;
        int i0c = min(max(i0, 0), T - 1);
        int i1c = min(max(i1, 0), T - 1);

        int j0 = i0c - t0 + 1, j1 = i1c - t0 + 1;
        const float* p0 = (j0 >= 0 && j0 < DSTG)
            ? xs + (size_t)j0 * CCH
            : Xl + ((size_t)(b << logT) + i0c) * CCH;
        const float* p1 = (j1 >= 0 && j1 < DSTG)
            ? xs + (size_t)j1 * CCH
            : Xl + ((size_t)(b << logT) + i1c) * CCH;

        size_t base = (size_t)m * KRED + (size_t)k * CCH;
        #pragma unroll
        for (int q = 0; q < 4; q++) {
            int ch = (lane + q * 32) * 4;
            float4 a = *(const float4*)(p0 + ch);
            float4 c = *(const float4*)(p1 + ch);
            float e0 = w0 * a.x + w1 * c.x;
            float e1 = w0 * a.y + w1 * c.y;
            float e2 = w0 * a.z + w1 * c.z;
            float e3 = w0 * a.w + w1 * c.w;

            __nv_bfloat162 h01 = __floats2bfloat162_rn(e0, e1);
            __nv_bfloat162 h23 = __floats2bfloat162_rn(e2, e3);
            float2 f01 = __bfloat1622float2(h01);
            float2 f23 = __bfloat1622float2(h23);
            __nv_bfloat162 l01 = __floats2bfloat162_rn(e0 - f01.x, e1 - f01.y);
            __nv_bfloat162 l23 = __floats2bfloat162_rn(e2 - f23.x, e3 - f23.y);

            uint2 hv, lvv;
            hv.x = *reinterpret_cast<uint32_t*>(&h01);
            hv.y = *reinterpret_cast<uint32_t*>(&h23);
            lvv.x = *reinterpret_cast<uint32_t*>(&l01);
            lvv.y = *reinterpret_cast<uint32_t*>(&l23);
            *(uint2*)(Ah + base + ch) = hv;
            *(uint2*)(Al + base + ch) = lvv;
        }
    }
}

// ---------------------------------------------------------------------------
// GEMM: Y[m,n] = relu( (Ah@Wh + Ah@Wl + Al@Wh)[m,n] + bias[n] ) * maskrow[m]
// grid (4, 448), 128 threads (4 warps, warp tile 64x32), 2-stage, 4 CTAs/SM.
// Inner loop: 3 passes over n8 so consecutive MMAs hit different accumulators.
// TRANS_OUT: write (B,C,T) layout directly into the final output buffer.
template <bool TRANS_OUT>
__global__ __launch_bounds__(128, 4)
void gemm_mma_kernel(const __nv_bfloat16* __restrict__ Ahg,
                     const __nv_bfloat16* __restrict__ Alg,
                     const __nv_bfloat16* __restrict__ Whg,
                     const __nv_bfloat16* __restrict__ Wlg,
                     const float* __restrict__ bias,
                     const float* __restrict__ maskrow,
                     float* __restrict__ Y) {
    extern __shared__ __nv_bfloat16 sm[];
    uint32_t sbase = smem_u32(sm);
    int tid = threadIdx.x, warp = tid >> 5, lane = tid & 31;
    int m0 = blockIdx.y * BMM, n0 = blockIdx.x * BNN;

    const uint32_t offAl = A_ELE * 2;
    const uint32_t offBh = 2 * A_ELE * 2;
    const uint32_t offBl = offBh + B_ELE * 2;

    int ar0 = tid >> 2, akc = (tid & 3) * 8;
    int br0 = tid >> 4, bnc = (tid & 15) * 8;
    const __nv_bfloat16* gAh = Ahg + (size_t)(m0 + ar0) * KRED + akc;
    const __nv_bfloat16* gAl = Alg + (size_t)(m0 + ar0) * KRED + akc;
    const __nv_bfloat16* gBh = Whg + (size_t)br0 * CCH + n0 + bnc;
    const __nv_bfloat16* gBl = Wlg + (size_t)br0 * CCH + n0 + bnc;
    const uint32_t A2 = 32u * KRED;
    uint32_t sA0 = (uint32_t)(ar0 * AST + akc) * 2;
    uint32_t sA1 = sA0 + 32u * AST * 2;
    uint32_t sB0 = (uint32_t)(br0 * BST + bnc) * 2;

    int wn = warp * 32;
    int lr = lane & 15, lc = lane >> 4;
    uint32_t a_off[4], b_off[2];
    #pragma unroll
    for (int mt = 0; mt < 4; mt++)
        a_off[mt] = (uint32_t)((mt * 16 + lr) * AST + lc * 8) * 2;
    #pragma unroll
    for (int nt = 0; nt < 2; nt++)
        b_off[nt] = (uint32_t)(lr * BST + wn + nt * 16 + lc * 8) * 2;

    float acc[4][4][4];
    #pragma unroll
    for (int i = 0; i < 4; i++)
        #pragma unroll
        for (int j = 0; j < 4; j++)
            #pragma unroll
            for (int q = 0; q < 4; q++) acc[i][j][q] = 0.f;

    auto load_stage = [&](int st, int k0) {
        uint32_t sb = sbase + (uint32_t)st * STG_BYTES;
        CP16(sb + sA0, gAh + k0);
        CP16(sb + sA1, gAh + A2 + k0);
        CP16(sb + offAl + sA0, gAl + k0);
        CP16(sb + offAl + sA1, gAl + A2 + k0);
        #pragma unroll
        for (int c = 0; c < 4; c++) {
            uint32_t so = sB0 + (uint32_t)c * 8 * BST * 2;
            size_t go = (size_t)(k0 + c * 8) * CCH;
            CP16(sb + offBh + so, gBh + go);
            CP16(sb + offBl + so, gBl + go);
        }
    };

    load_stage(0, 0);
    CP_COMMIT();
    CP_WAIT0();
    __syncthreads();

    for (int it = 0; it < KITERS; it++) {
        if (it + 1 < KITERS) {
            load_stage((it + 1) & 1, (it + 1) * BKK);
            CP_COMMIT();
        }

        uint32_t sb = sbase + (uint32_t)(it & 1) * STG_BYTES;

        uint32_t bh[2][2][4], bl[2][2][4];
        #pragma unroll
        for (int ks = 0; ks < 2; ks++)
            #pragma unroll
            for (int nt = 0; nt < 2; nt++) {
                ldsm_x4_t(bh[nt][ks], sb + offBh + b_off[nt] + ks * (16 * BST * 2));
                ldsm_x4_t(bl[nt][ks], sb + offBl + b_off[nt] + ks * (16 * BST * 2));
            }

        #pragma unroll
        for (int mt = 0; mt < 4; mt++) {
            #pragma unroll
            for (int ks = 0; ks < 2; ks++) {
                uint32_t ah[4], al[4];
                ldsm_x4(ah, sb + a_off[mt] + ks * 32);
                ldsm_x4(al, sb + offAl + a_off[mt] + ks * 32);
                // pass 0: ah @ Wh  (4 independent accumulators)
                #pragma unroll
                for (int n8 = 0; n8 < 4; n8++)
                    mma16816(acc[mt][n8], ah, &bh[n8 >> 1][ks][(n8 & 1) * 2]);
                // pass 1: ah @ Wl
                #pragma unroll
                for (int n8 = 0; n8 < 4; n8++)
                    mma16816(acc[mt][n8], ah, &bl[n8 >> 1][ks][(n8 & 1) * 2]);
                // pass 2: al @ Wh
                #pragma unroll
                for (int n8 = 0; n8 < 4; n8++)
                    mma16816(acc[mt][n8], al, &bh[n8 >> 1][ks][(n8 & 1) * 2]);
            }
        }

        if (it + 1 < KITERS) {
            CP_WAIT0();
            __syncthreads();
        }
    }

    if (!TRANS_OUT) {
        #pragma unroll
        for (int mt = 0; mt < 4; mt++) {
            int r0g = m0 + mt * 16 + (lane >> 2);
            float mv0 = maskrow[r0g], mv1 = maskrow[r0g + 8];
            float* y0 = Y + (size_t)r0g * CCH;
            float* y1 = y0 + (size_t)8 * CCH;
            #pragma unroll
            for (int n8 = 0; n8 < 4; n8++) {
                int c0g = n0 + wn + n8 * 8 + (lane & 3) * 2;
                float b0 = bias[c0g], b1 = bias[c0g + 1];
                float2 v0, v1;
                v0.x = fmaxf(acc[mt][n8][0] + b0, 0.f) * mv0;
                v0.y = fmaxf(acc[mt][n8][1] + b1, 0.f) * mv0;
                v1.x = fmaxf(acc[mt][n8][2] + b0, 0.f) * mv1;
                v1.y = fmaxf(acc[mt][n8][3] + b1, 0.f) * mv1;
                *(float2*)(y0 + c0g) = v0;
                *(float2*)(y1 + c0g) = v1;
            }
        }
    } else {
        float* smT = (float*)sm;
        __syncthreads();
        #pragma unroll
        for (int mt = 0; mt < 4; mt++) {
            int ml0 = mt * 16 + (lane >> 2);
            int r0g = m0 + ml0;
            float mv0 = maskrow[r0g], mv1 = maskrow[r0g + 8];
            #pragma unroll
            for (int n8 = 0; n8 < 4; n8++) {
                int cl = wn + n8 * 8 + (lane & 3) * 2;
                float b0 = bias[n0 + cl], b1 = bias[n0 + cl + 1];
                smT[cl * TPAD + ml0]           = fmaxf(acc[mt][n8][0] + b0, 0.f) * mv0;
                smT[(cl + 1) * TPAD + ml0]     = fmaxf(acc[mt][n8][1] + b1, 0.f) * mv0;
                smT[cl * TPAD + ml0 + 8]       = fmaxf(acc[mt][n8][2] + b0, 0.f) * mv1;
                smT[(cl + 1) * TPAD + ml0 + 8] = fmaxf(acc[mt][n8][3] + b1, 0.f) * mv1;
            }
        }
        __syncthreads();
        int lv = (m0 < LV0) ? 0 : (m0 < LV01 ? 1 : 2);
        int lbase = (lv == 0) ? 0 : (lv == 1 ? LV0 : LV01);
        int logT = 11 - lv;
        int T = 1 << logT;
        int rl0 = m0 - lbase;
        int b = rl0 >> logT, t0 = rl0 & (T - 1);
        size_t obase = (lv == 0) ? 0 : (lv == 1 ? (size_t)BSZ * CCH * 2048
                                               : (size_t)BSZ * CCH * 3072);
        float* outb = Y + obase + ((size_t)b * CCH) * T + t0;
        for (int idx = tid; idx < 128 * 16; idx += 128) {
            int cl = idx >> 4, seg = (idx & 15) * 4;
            float4 v = *(float4*)(smT + cl * TPAD + seg);
            *(float4*)(outb + (size_t)(n0 + cl) * T + seg) = v;
        }
    }
}

// ---------------------------------------------------------------------------
extern "C" void kernel_launch(void* const* d_in, const int* in_sizes, int n_in,
                              void* d_out, int out_size) {
    const float *feats[3] = {}, *masks[3] = {}, *offs[3] = {};
    const float *w[2] = {}, *bias[2] = {}, *ow[2] = {}, *ob[2] = {};
    int wi = 0, bi = 0, owi = 0, obi = 0;
    for (int i = 0; i < n_in; i++) {
        const float* p = (const float*)d_in[i];
        switch (in_sizes[i]) {
            case 8 * 512 * 2048: feats[0] = p; break;
            case 8 * 512 * 1024: feats[1] = p; break;
            case 8 * 512 * 512:  feats[2] = p; break;
            case 8 * 2048:       masks[0] = p; break;
            case 8 * 1024:       masks[1] = p; break;
            case 8 * 512:        masks[2] = p; break;
            case 8 * 3 * 2048:   offs[0] = p; break;
            case 8 * 3 * 1024:   offs[1] = p; break;
            case 8 * 3 * 512:    offs[2] = p; break;
            case 512 * 512 * 3:  if (wi < 2)  w[wi++] = p; break;
            case 512:            if (bi < 2)  bias[bi++] = p; break;
            case 3 * 512 * 3:    if (owi < 2) ow[owi++] = p; break;
            case 3:              if (obi < 2) ob[obi++] = p; break;
            default: break;
        }
    }

    float *xb, *yb, *offa, *mrow, *ow2;
    __nv_bfloat16 *Ah, *Al, *Wh, *Wl;
    cudaGetSymbolAddress((void**)&xb, g_x);
    cudaGetSymbolAddress((void**)&yb, g_y);
    cudaGetSymbolAddress((void**)&offa, g_offa);
    cudaGetSymbolAddress((void**)&mrow, g_mrow);
    cudaGetSymbolAddress((void**)&ow2, g_ow2);
    cudaGetSymbolAddress((void**)&Ah, g_Ah);
    cudaGetSymbolAddress((void**)&Al, g_Al);
    cudaGetSymbolAddress((void**)&Wh, g_Wh);
    cudaGetSymbolAddress((void**)&Wl, g_Wl);
    float* out = (float*)d_out;

    cudaFuncSetAttribute(gemm_mma_kernel<false>,
                         cudaFuncAttributeMaxDynamicSharedMemorySize, GEMM_SMEM);
    cudaFuncSetAttribute(gemm_mma_kernel<true>,
                         cudaFuncAttributeMaxDynamicSharedMemorySize, GEMM_SMEM);
    cudaFuncSetAttribute(deform_kernel<true>,
                         cudaFuncAttributeMaxDynamicSharedMemorySize, DEF_SMEM);
    cudaFuncSetAttribute(deform_kernel<false>,
                         cudaFuncAttributeMaxDynamicSharedMemorySize, DEF_SMEM);

    // launch 0: input transposes; launch 1: weight split + masks
    tin_kernel<<<TIN_BLOCKS, 256>>>(feats[0], feats[1], feats[2], xb);
    wsplit_kernel<<<(WSPLIT_TOTAL + 255) / 256, 256>>>(
        w[0], w[1], ow[0], ow[1], masks[0], masks[1], masks[2],
        Wh, Wl, ow2, mrow, out);

    // ---- layer 0 ----  (launches 2,3 — ncu captures launch 3 = gemm<false>)
    deform_kernel<true><<<ROWS_TOTAL / DROWS, 128, DEF_SMEM>>>(
        xb, offs[0], offs[1], offs[2], ow2, ob[0], offa, Ah, Al);
    gemm_mma_kernel<false><<<dim3(4, ROWS_TOTAL / BMM), 128, GEMM_SMEM>>>(
        Ah, Al, Wh, Wl, bias[0], mrow, yb);

    // ---- layer 1 ----  (launches 4,5)
    deform_kernel<false><<<ROWS_TOTAL / DROWS, 128, DEF_SMEM>>>(
        yb, offa, nullptr, nullptr, ow2 + KT * KT * CCH, ob[1], nullptr, Ah, Al);
    gemm_mma_kernel<true><<<dim3(4, ROWS_TOTAL / BMM), 128, GEMM_SMEM>>>(
        Ah, Al, Wh + (size_t)KRED * CCH, Wl + (size_t)KRED * CCH,
        bias[1], mrow, out);
}